// round 10
// baseline (speedup 1.0000x reference)
#include <cuda_runtime.h>
#include <cuda_fp16.h>
#include <math.h>
#include <stdint.h>

#define NN 8192
#define DD 64
#define NSPLIT 4
#define MT 128          // rows per CTA
#define JT 128          // j tile
#define JSPAN (NN / NSPLIT)        // 2048 j's per CTA
#define NTILE (JSPAN / JT)         // 16 j-tiles per CTA
#define SGS 136         // padded sG row stride (halves)

// ---- static device scratch (no allocation allowed) ----
__device__ float  g_G[NN * DD];            // G = relu(X@W+b)@wt (fp32, row-major)
__device__ __half g_GT[DD * NN];           // G transposed, fp16 (feature-major)
__device__ float  g_V[NN * DD];            // layer-1 output
__device__ float  g_num[NSPLIT * NN * DD]; // numerator partials
__device__ float  g_den[NSPLIT * NN];      // denominator partials (pass1 only)
__device__ float2 g_ep[NN];                // scaled (eta*s, phi*s)
__device__ float  g_part[64 * 64];
// weight-fragment cache: identical S for both layers. 8.4M uint4 = 134MB.
__device__ uint4  g_wc[64 * 8 * NSPLIT * NTILE * 8 * 32];

// ============================================================
// ep: pack (eta, phi), pre-scaled by s = sqrt(alpha * log2(e))
// ============================================================
__global__ void ep_kernel(const float* __restrict__ x, const float* __restrict__ alpha) {
    const float LOG2E = 1.44269504088896340736f;
    float s = sqrtf(alpha[0] * LOG2E);
    int j = blockIdx.x * 256 + threadIdx.x;
    g_ep[j] = make_float2(x[j * 7 + 1] * s, x[j * 7 + 2] * s);
}

// ============================================================
// prep v2: G = relu(X@W+b)@wt, weights in SMEM, 4 cols/thread via
// float4 LDS. 16 row-slots x 16 col-groups, 32 rows/CTA, low regs.
// ============================================================
template<int DIN>
__global__ __launch_bounds__(256) void prep_kernel(
    const float* __restrict__ Xext, const float* __restrict__ W,
    const float* __restrict__ b, const float* __restrict__ wt)
{
    __shared__ float sW[DIN * 64];
    __shared__ float swt[64 * 64];
    __shared__ float sx[16][(DIN <= 8) ? 8 : 64];
    __shared__ float sh[16][64];
    __shared__ __half sgt[32][64];

    const int tid = threadIdx.x;
    const int rs = tid >> 4;       // row slot 0..15
    const int cg = tid & 15;       // col group (4 cols)
    const float* X = Xext ? Xext : g_V;
    const int rowbase = blockIdx.x * 32;

    // cooperative weight loads (float4)
    for (int t = tid; t < DIN * 16; t += 256)
        ((float4*)sW)[t] = ((const float4*)W)[t];
    for (int t = tid; t < 64 * 16; t += 256)
        ((float4*)swt)[t] = ((const float4*)wt)[t];
    const float4 bk4 = *(const float4*)&b[cg * 4];
    __syncthreads();

    #pragma unroll
    for (int half = 0; half < 2; half++) {
        const int row = rowbase + half * 16 + rs;
        // load X row into sx
        if (DIN <= 8) {
            if (cg < DIN) sx[rs][cg] = X[row * DIN + cg];
        } else {
            *(float4*)&sx[rs][cg * 4] = *(const float4*)&X[row * DIN + cg * 4];
        }
        __syncthreads();
        // stage 1: h = relu(x @ W + b), 4 cols per thread
        float a0 = bk4.x, a1 = bk4.y, a2 = bk4.z, a3 = bk4.w;
        #pragma unroll
        for (int d = 0; d < DIN; d++) {
            float xv = sx[rs][d];
            float4 w4 = *(const float4*)&sW[d * 64 + cg * 4];
            a0 = fmaf(xv, w4.x, a0); a1 = fmaf(xv, w4.y, a1);
            a2 = fmaf(xv, w4.z, a2); a3 = fmaf(xv, w4.w, a3);
        }
        *(float4*)&sh[rs][cg * 4] = make_float4(fmaxf(a0, 0.f), fmaxf(a1, 0.f),
                                                fmaxf(a2, 0.f), fmaxf(a3, 0.f));
        __syncthreads();
        // stage 2: g = h @ wt, 4 cols per thread
        float g0 = 0.f, g1 = 0.f, g2 = 0.f, g3 = 0.f;
        #pragma unroll
        for (int m = 0; m < 64; m++) {
            float hv = sh[rs][m];
            float4 w4 = *(const float4*)&swt[m * 64 + cg * 4];
            g0 = fmaf(hv, w4.x, g0); g1 = fmaf(hv, w4.y, g1);
            g2 = fmaf(hv, w4.z, g2); g3 = fmaf(hv, w4.w, g3);
        }
        *(float4*)&g_G[row * 64 + cg * 4] = make_float4(g0, g1, g2, g3);
        sgt[half * 16 + rs][cg * 4 + 0] = __float2half(g0);
        sgt[half * 16 + rs][cg * 4 + 1] = __float2half(g1);
        sgt[half * 16 + rs][cg * 4 + 2] = __float2half(g2);
        sgt[half * 16 + rs][cg * 4 + 3] = __float2half(g3);
    }
    __syncthreads();
    // coalesced transposed store: g_GT[k][rowbase..rowbase+31]
    const int kk = tid >> 2, seg = tid & 3;
    __half tmp[8];
    #pragma unroll
    for (int r = 0; r < 8; r++) tmp[r] = sgt[seg * 8 + r][kk];
    *(float4*)(g_GT + kk * NN + rowbase + seg * 8) = *(float4*)tmp;
}

// ============================================================
// drn = log2(log2e) - alpha*log2e*dR^2  (coords pre-scaled), so that
// w = exp(exp(-alpha dR^2)) = 2^(2^drn)
// ============================================================
__device__ __forceinline__ float drnfun(float ei, float pii, float ex, float px, float tps) {
    const float LL = 0.52876637294489770f;   // log2(log2(e))
    float de = ei - ex;
    float d  = pii - px;
    float ad = fabsf(d);
    float dp = fminf(ad, tps - ad);
    return fmaf(de, -de, fmaf(dp, -dp, LL));
}

// pack two drn -> half2 weights {lo=w0, hi=w1} via two packed ex2
__device__ __forceinline__ uint32_t wpair(float drn0, float drn1) {
    uint32_t r;
    asm("{\n\t.reg .b32 t;\n\t"
        "cvt.rn.f16x2.f32 t, %2, %1;\n\t"
        "ex2.approx.f16x2 t, t;\n\t"
        "ex2.approx.f16x2 %0, t;\n\t}"
        : "=r"(r) : "f"(drn0), "f"(drn1));
    return r;
}

// ============================================================
// pass: S@G on HMMA. GEN=1: compute weights (packed ex2), cache
// fragments, den via extra MMA against constant ones-B.
// GEN=0: replay cached fragments, skip weight math and den.
// ============================================================
template<int GEN>
__global__ __launch_bounds__(256, 2) void pass_kernel(const float* __restrict__ alpha)
{
    __shared__ __half sG[64 * SGS];   // [feature][j] padded
    __shared__ float2 sEP[JT];

    const int tid = threadIdx.x;
    const int warp = tid >> 5, lane = tid & 31;
    const int gid = lane >> 2, tig = lane & 3;
    const int rowtile = blockIdx.x, jsplit = blockIdx.y;
    const int j0base = jsplit * JSPAN;

    const int row0 = rowtile * MT + warp * 16 + gid;

    float tps = 0.f, e0x = 0.f, e0y = 0.f, e1x = 0.f, e1y = 0.f;
    if (GEN) {
        const float LOG2E = 1.44269504088896340736f;
        const float TWOPI = 6.28318530717958647692f;
        tps = TWOPI * sqrtf(alpha[0] * LOG2E);
        float2 e0 = g_ep[row0]; e0x = e0.x; e0y = e0.y;
        float2 e1 = g_ep[row0 + 8]; e1x = e1.x; e1y = e1.y;
    }

    // weight-cache base for this (rowtile, warp, jsplit), lane-major
    uint4* wcp = g_wc + ((((size_t)rowtile * 8 + warp) * NSPLIT + jsplit) * (NTILE * 8)) * 32 + lane;

    // ldmatrix per-lane address offset (halves)
    const int m = lane >> 3;
    const int bro = ((m >> 1) * 8 + (lane & 7)) * SGS + (m & 1) * 8;

    uint32_t sgb;
    asm("{ .reg .u64 t; cvta.to.shared.u64 t, %1; cvt.u32.u64 %0, t; }" : "=r"(sgb) : "l"(sG));

    float acc[8][4];
    #pragma unroll
    for (int nt = 0; nt < 8; nt++)
        #pragma unroll
        for (int q = 0; q < 4; q++) acc[nt][q] = 0.f;
    float accd[4] = {0.f, 0.f, 0.f, 0.f};   // den accumulator (GEN only)

    for (int t = 0; t < NTILE; t++) {
        const int j0 = j0base + t * JT;
        __syncthreads();
        #pragma unroll
        for (int i = 0; i < 4; i++) {
            int idx = tid + i * 256;
            int f = idx >> 4, c = idx & 15;
            *(float4*)(sG + f * SGS + c * 8) = *(const float4*)(g_GT + f * NN + j0 + c * 8);
        }
        if (GEN && tid < 64)
            ((float4*)sEP)[tid] = ((const float4*)((const float*)g_ep + j0 * 2))[tid];
        __syncthreads();

        uint4 wf[8];
        if (!GEN) {
            #pragma unroll
            for (int ks = 0; ks < 8; ks++)
                wf[ks] = wcp[(t * 8 + ks) * 32];
        }

        #pragma unroll
        for (int ks = 0; ks < 8; ks++) {
            const int jj = ks * 16;
            uint32_t af0, af1, af2, af3;
            if (GEN) {
                float4 p0 = *(const float4*)(&sEP[jj + tig * 2]);
                float4 p1 = *(const float4*)(&sEP[jj + 8 + tig * 2]);
                float dn00 = drnfun(e0x, e0y, p0.x, p0.y, tps);
                float dn01 = drnfun(e0x, e0y, p0.z, p0.w, tps);
                float dn10 = drnfun(e1x, e1y, p0.x, p0.y, tps);
                float dn11 = drnfun(e1x, e1y, p0.z, p0.w, tps);
                float dn02 = drnfun(e0x, e0y, p1.x, p1.y, tps);
                float dn03 = drnfun(e0x, e0y, p1.z, p1.w, tps);
                float dn12 = drnfun(e1x, e1y, p1.x, p1.y, tps);
                float dn13 = drnfun(e1x, e1y, p1.z, p1.w, tps);
                af0 = wpair(dn00, dn01);
                af1 = wpair(dn10, dn11);
                af2 = wpair(dn02, dn03);
                af3 = wpair(dn12, dn13);
                wcp[(t * 8 + ks) * 32] = make_uint4(af0, af1, af2, af3);
                // den: MMA against constant all-ones B fragment
                asm volatile(
                    "mma.sync.aligned.m16n8k16.row.col.f32.f16.f16.f32 "
                    "{%0,%1,%2,%3}, {%4,%5,%6,%7}, {%8,%8}, {%0,%1,%2,%3};"
                    : "+f"(accd[0]), "+f"(accd[1]), "+f"(accd[2]), "+f"(accd[3])
                    : "r"(af0), "r"(af1), "r"(af2), "r"(af3), "r"(0x3C003C00u));
            } else {
                af0 = wf[ks].x; af1 = wf[ks].y; af2 = wf[ks].z; af3 = wf[ks].w;
            }

            // two half-groups of (2 ldmatrix.x4 + 4 MMA) to cap live regs
            #pragma unroll
            for (int h = 0; h < 2; h++) {
                uint32_t bf[4][2];
                #pragma unroll
                for (int q = 0; q < 2; q++) {
                    uint32_t addr = sgb + (uint32_t)((h * 2 + q) * 16 * SGS + bro + jj) * 2u;
                    asm volatile("ldmatrix.sync.aligned.m8n8.x4.shared.b16 {%0,%1,%2,%3}, [%4];"
                        : "=r"(bf[2 * q][0]), "=r"(bf[2 * q][1]),
                          "=r"(bf[2 * q + 1][0]), "=r"(bf[2 * q + 1][1])
                        : "r"(addr));
                }
                #pragma unroll
                for (int nt = 0; nt < 4; nt++) {
                    asm volatile(
                        "mma.sync.aligned.m16n8k16.row.col.f32.f16.f16.f32 "
                        "{%0,%1,%2,%3}, {%4,%5,%6,%7}, {%8,%9}, {%0,%1,%2,%3};"
                        : "+f"(acc[h * 4 + nt][0]), "+f"(acc[h * 4 + nt][1]),
                          "+f"(acc[h * 4 + nt][2]), "+f"(acc[h * 4 + nt][3])
                        : "r"(af0), "r"(af1), "r"(af2), "r"(af3),
                          "r"(bf[nt][0]), "r"(bf[nt][1]));
                }
            }
        }
    }

    if (GEN && tig == 0) {
        g_den[jsplit * NN + row0] = accd[0];
        g_den[jsplit * NN + row0 + 8] = accd[2];
    }

    float* np = g_num + (size_t)jsplit * NN * DD;
    #pragma unroll
    for (int nt = 0; nt < 8; nt++) {
        *(float2*)(np + (size_t)row0 * DD + nt * 8 + tig * 2) =
            make_float2(acc[nt][0], acc[nt][1]);
        *(float2*)(np + (size_t)(row0 + 8) * DD + nt * 8 + tig * 2) =
            make_float2(acc[nt][2], acc[nt][3]);
    }
}

// ============================================================
// finalize (layer 1): V = relu(num/den + G + bs)
// ============================================================
__global__ __launch_bounds__(256) void finalize_kernel(const float* __restrict__ bs)
{
    int gid = blockIdx.x * 256 + threadIdx.x;
    int i = gid >> 6;
    float ds = 0.f, ns = 0.f;
    #pragma unroll
    for (int s = 0; s < NSPLIT; s++) {
        ds += g_den[s * NN + i];
        ns += g_num[(size_t)s * NN * DD + gid];
    }
    float v = ns / ds + g_G[gid] + bs[0];
    g_V[gid] = fmaxf(v, 0.f);
}

// ============================================================
// reduce (finalize2 fused): column sums of relu(num/den + G + bs)
// ============================================================
__global__ __launch_bounds__(256) void reduce_kernel(const float* __restrict__ bs)
{
    __shared__ float s[4][64];
    int tid = threadIdx.x;
    int k = tid & 63;
    int rg = tid >> 6;
    int bkt = blockIdx.x;
    float acc = 0.f;
    for (int r = rg; r < 128; r += 4) {
        int row = bkt * 128 + r;
        float ds = 0.f, ns = 0.f;
        #pragma unroll
        for (int sp = 0; sp < NSPLIT; sp++) {
            ds += g_den[sp * NN + row];
            ns += g_num[(size_t)sp * NN * DD + (size_t)row * DD + k];
        }
        float v = ns / ds + g_G[row * 64 + k] + bs[0];
        acc += fmaxf(v, 0.f);
    }
    s[rg][k] = acc;
    __syncthreads();
    if (tid < 64)
        g_part[bkt * 64 + tid] = s[0][tid] + s[1][tid] + s[2][tid] + s[3][tid];
}

__global__ void head_kernel(const float* __restrict__ Wl,
                            const float* __restrict__ bl,
                            float* __restrict__ out)
{
    __shared__ float sv[64];
    int t = threadIdx.x;
    float sk = 0.f;
    for (int b = 0; b < 64; b++) sk += g_part[b * 64 + t];
    sv[t] = sk * Wl[t];
    __syncthreads();
    if (t == 0) {
        float s = 0.f;
        for (int i = 0; i < 64; i++) s += sv[i];
        s += bl[0];
        out[0] = 1.f / (1.f + expf(-s));
    }
}

extern "C" void kernel_launch(void* const* d_in, const int* in_sizes, int n_in,
                              void* d_out, int out_size)
{
    const float* x     = (const float*)d_in[0];
    const float* alpha = (const float*)d_in[1];
    const float* W1    = (const float*)d_in[2];
    const float* b1    = (const float*)d_in[3];
    const float* wt1   = (const float*)d_in[4];
    const float* bs1   = (const float*)d_in[5];
    const float* W2    = (const float*)d_in[6];
    const float* b2    = (const float*)d_in[7];
    const float* wt2   = (const float*)d_in[8];
    const float* bs2   = (const float*)d_in[9];
    const float* Wl    = (const float*)d_in[10];
    const float* bl    = (const float*)d_in[11];
    float* out = (float*)d_out;

    dim3 pg(NN / MT, NSPLIT);

    ep_kernel<<<NN / 256, 256>>>(x, alpha);
    // layer 1: generate + cache weight fragments
    prep_kernel<7><<<NN / 32, 256>>>(x, W1, b1, wt1);
    pass_kernel<1><<<pg, 256>>>(alpha);
    finalize_kernel<<<NN * DD / 256, 256>>>(bs1);
    // layer 2: replay cached fragments (den reused from layer 1)
    prep_kernel<64><<<NN / 32, 256>>>(nullptr, W2, b2, wt2);
    pass_kernel<0><<<pg, 256>>>(alpha);
    // head: finalize2 fused into reduce
    reduce_kernel<<<64, 256>>>(bs2);
    head_kernel<<<1, 64>>>(Wl, bl, out);
}

// round 11
// speedup vs baseline: 1.0029x; 1.0029x over previous
#include <cuda_runtime.h>
#include <cuda_fp16.h>
#include <math.h>
#include <stdint.h>

#define NN 8192
#define DD 64
#define NSPLIT 4
#define MT 128          // rows per CTA
#define JT 128          // j tile
#define JSPAN (NN / NSPLIT)        // 2048 j's per CTA
#define NTILE (JSPAN / JT)         // 16 j-tiles per CTA
#define SGS 136         // padded sG row stride (halves)

// ---- static device scratch (no allocation allowed) ----
__device__ float  g_G[NN * DD];            // G = relu(X@W+b)@wt (fp32, row-major)
__device__ __half g_GT[DD * NN];           // G transposed, fp16 (feature-major)
__device__ float  g_V[NN * DD];            // layer-1 output
__device__ float  g_num[NSPLIT * NN * DD]; // numerator partials
__device__ float  g_den[NSPLIT * NN];      // denominator partials (pass1 only)
__device__ __half g_ephe[NN];              // scaled eta (fp16)
__device__ __half g_ephp[NN];              // scaled phi (fp16)
__device__ float  g_part[64 * 64];
// weight-fragment cache: identical S for both layers. 8.4M uint4 = 134MB.
__device__ uint4  g_wc[64 * 8 * NSPLIT * NTILE * 8 * 32];

// ============================================================
// ep: scaled fp16 SoA coords.  s = sqrt(alpha*log2e) so that
// 2^(-(de^2+dp^2)) == exp(-alpha*dR^2)
// ============================================================
__global__ void ep_kernel(const float* __restrict__ x, const float* __restrict__ alpha) {
    const float LOG2E = 1.44269504088896340736f;
    float s = sqrtf(alpha[0] * LOG2E);
    int j = blockIdx.x * 256 + threadIdx.x;
    g_ephe[j] = __float2half(x[j * 7 + 1] * s);
    g_ephp[j] = __float2half(x[j * 7 + 2] * s);
}

// ============================================================
// prep v2: G = relu(X@W+b)@wt, weights in SMEM, 4 cols/thread via
// float4 LDS. 16 row-slots x 16 col-groups, 32 rows/CTA, low regs.
// ============================================================
template<int DIN>
__global__ __launch_bounds__(256) void prep_kernel(
    const float* __restrict__ Xext, const float* __restrict__ W,
    const float* __restrict__ b, const float* __restrict__ wt)
{
    __shared__ float sW[DIN * 64];
    __shared__ float swt[64 * 64];
    __shared__ float sx[16][(DIN <= 8) ? 8 : 64];
    __shared__ float sh[16][64];
    __shared__ __half sgt[32][64];

    const int tid = threadIdx.x;
    const int rs = tid >> 4;       // row slot 0..15
    const int cg = tid & 15;       // col group (4 cols)
    const float* X = Xext ? Xext : g_V;
    const int rowbase = blockIdx.x * 32;

    // cooperative weight loads (float4)
    for (int t = tid; t < DIN * 16; t += 256)
        ((float4*)sW)[t] = ((const float4*)W)[t];
    for (int t = tid; t < 64 * 16; t += 256)
        ((float4*)swt)[t] = ((const float4*)wt)[t];
    const float4 bk4 = *(const float4*)&b[cg * 4];
    __syncthreads();

    #pragma unroll
    for (int half = 0; half < 2; half++) {
        const int row = rowbase + half * 16 + rs;
        // load X row into sx
        if (DIN <= 8) {
            if (cg < DIN) sx[rs][cg] = X[row * DIN + cg];
        } else {
            *(float4*)&sx[rs][cg * 4] = *(const float4*)&X[row * DIN + cg * 4];
        }
        __syncthreads();
        // stage 1: h = relu(x @ W + b), 4 cols per thread
        float a0 = bk4.x, a1 = bk4.y, a2 = bk4.z, a3 = bk4.w;
        #pragma unroll
        for (int d = 0; d < DIN; d++) {
            float xv = sx[rs][d];
            float4 w4 = *(const float4*)&sW[d * 64 + cg * 4];
            a0 = fmaf(xv, w4.x, a0); a1 = fmaf(xv, w4.y, a1);
            a2 = fmaf(xv, w4.z, a2); a3 = fmaf(xv, w4.w, a3);
        }
        *(float4*)&sh[rs][cg * 4] = make_float4(fmaxf(a0, 0.f), fmaxf(a1, 0.f),
                                                fmaxf(a2, 0.f), fmaxf(a3, 0.f));
        __syncthreads();
        // stage 2: g = h @ wt, 4 cols per thread
        float g0 = 0.f, g1 = 0.f, g2 = 0.f, g3 = 0.f;
        #pragma unroll
        for (int m = 0; m < 64; m++) {
            float hv = sh[rs][m];
            float4 w4 = *(const float4*)&swt[m * 64 + cg * 4];
            g0 = fmaf(hv, w4.x, g0); g1 = fmaf(hv, w4.y, g1);
            g2 = fmaf(hv, w4.z, g2); g3 = fmaf(hv, w4.w, g3);
        }
        *(float4*)&g_G[row * 64 + cg * 4] = make_float4(g0, g1, g2, g3);
        sgt[half * 16 + rs][cg * 4 + 0] = __float2half(g0);
        sgt[half * 16 + rs][cg * 4 + 1] = __float2half(g1);
        sgt[half * 16 + rs][cg * 4 + 2] = __float2half(g2);
        sgt[half * 16 + rs][cg * 4 + 3] = __float2half(g3);
    }
    __syncthreads();
    // coalesced transposed store: g_GT[k][rowbase..rowbase+31]
    const int kk = tid >> 2, seg = tid & 3;
    __half tmp[8];
    #pragma unroll
    for (int r = 0; r < 8; r++) tmp[r] = sgt[seg * 8 + r][kk];
    *(float4*)(g_GT + kk * NN + rowbase + seg * 8) = *(float4*)tmp;
}

// ============================================================
// wgen: half2-packed weights for a j-pair.
// drn = LL - de^2 - dp^2 ; w = 2^(2^drn) = exp(exp(-alpha dR^2))
// ============================================================
__device__ __forceinline__ uint32_t wgen(half2 ei, half2 pi, half2 ej, half2 pj,
                                         half2 tps2, half2 LL2) {
    half2 de = __hsub2(ei, ej);
    half2 d  = __hsub2(pi, pj);
    half2 ad = __habs2(d);
    half2 dp = __hmin2(ad, __hsub2(tps2, ad));
    half2 s  = __hfma2(dp, dp, __hmul2(de, de));
    half2 drn = __hsub2(LL2, s);
    uint32_t r;
    asm("{\n\t.reg .b32 t;\n\t"
        "ex2.approx.f16x2 t, %1;\n\t"
        "ex2.approx.f16x2 %0, t;\n\t}"
        : "=r"(r) : "r"(*(uint32_t*)&drn));
    return r;
}

// ============================================================
// pass: S@G on HMMA. GEN=1: half2 weight gen, cache fragments,
// den via extra MMA vs ones-B.  GEN=0: replay cached fragments.
// ============================================================
template<int GEN>
__global__ __launch_bounds__(256, (GEN ? 3 : 2)) void pass_kernel(const float* __restrict__ alpha)
{
    __shared__ __half sG[64 * SGS];   // [feature][j] padded
    __shared__ __half sEe[JT];
    __shared__ __half sEp[JT];

    const int tid = threadIdx.x;
    const int warp = tid >> 5, lane = tid & 31;
    const int gid = lane >> 2, tig = lane & 3;
    const int rowtile = blockIdx.x, jsplit = blockIdx.y;
    const int j0base = jsplit * JSPAN;

    const int row0 = rowtile * MT + warp * 16 + gid;

    half2 ei0_2, pi0_2, ei1_2, pi1_2, tps2, LL2;
    if (GEN) {
        const float LOG2E = 1.44269504088896340736f;
        const float TWOPI = 6.28318530717958647692f;
        float tps = TWOPI * sqrtf(alpha[0] * LOG2E);
        tps2 = __half2half2(__float2half(tps));
        LL2  = __half2half2(__float2half(0.52876637294489770f));
        ei0_2 = __half2half2(g_ephe[row0]);
        pi0_2 = __half2half2(g_ephp[row0]);
        ei1_2 = __half2half2(g_ephe[row0 + 8]);
        pi1_2 = __half2half2(g_ephp[row0 + 8]);
    }

    // weight-cache base for this (rowtile, warp, jsplit), lane-major
    uint4* wcp = g_wc + ((((size_t)rowtile * 8 + warp) * NSPLIT + jsplit) * (NTILE * 8)) * 32 + lane;

    // ldmatrix per-lane address offset (halves)
    const int m = lane >> 3;
    const int bro = ((m >> 1) * 8 + (lane & 7)) * SGS + (m & 1) * 8;

    uint32_t sgb;
    asm("{ .reg .u64 t; cvta.to.shared.u64 t, %1; cvt.u32.u64 %0, t; }" : "=r"(sgb) : "l"(sG));

    float acc[8][4];
    #pragma unroll
    for (int nt = 0; nt < 8; nt++)
        #pragma unroll
        for (int q = 0; q < 4; q++) acc[nt][q] = 0.f;
    float accd[4] = {0.f, 0.f, 0.f, 0.f};   // den accumulator (GEN only)

    for (int t = 0; t < NTILE; t++) {
        const int j0 = j0base + t * JT;
        __syncthreads();
        #pragma unroll
        for (int i = 0; i < 4; i++) {
            int idx = tid + i * 256;
            int f = idx >> 4, c = idx & 15;
            *(float4*)(sG + f * SGS + c * 8) = *(const float4*)(g_GT + f * NN + j0 + c * 8);
        }
        if (GEN && tid < 32) {
            if (tid < 16)
                *(uint4*)(sEe + tid * 8) = *(const uint4*)(g_ephe + j0 + tid * 8);
            else
                *(uint4*)(sEp + (tid - 16) * 8) = *(const uint4*)(g_ephp + j0 + (tid - 16) * 8);
        }
        __syncthreads();

        uint4 wf[8];
        if (!GEN) {
            #pragma unroll
            for (int ks = 0; ks < 8; ks++)
                wf[ks] = wcp[(t * 8 + ks) * 32];
        }

        #pragma unroll
        for (int ks = 0; ks < 8; ks++) {
            const int jj = ks * 16;
            uint32_t af0, af1, af2, af3;
            if (GEN) {
                half2 ej0 = *(const half2*)(sEe + jj + tig * 2);
                half2 pj0 = *(const half2*)(sEp + jj + tig * 2);
                half2 ej1 = *(const half2*)(sEe + jj + 8 + tig * 2);
                half2 pj1 = *(const half2*)(sEp + jj + 8 + tig * 2);
                af0 = wgen(ei0_2, pi0_2, ej0, pj0, tps2, LL2);
                af1 = wgen(ei1_2, pi1_2, ej0, pj0, tps2, LL2);
                af2 = wgen(ei0_2, pi0_2, ej1, pj1, tps2, LL2);
                af3 = wgen(ei1_2, pi1_2, ej1, pj1, tps2, LL2);
                wcp[(t * 8 + ks) * 32] = make_uint4(af0, af1, af2, af3);
                // den: MMA against constant all-ones B fragment
                asm volatile(
                    "mma.sync.aligned.m16n8k16.row.col.f32.f16.f16.f32 "
                    "{%0,%1,%2,%3}, {%4,%5,%6,%7}, {%8,%8}, {%0,%1,%2,%3};"
                    : "+f"(accd[0]), "+f"(accd[1]), "+f"(accd[2]), "+f"(accd[3])
                    : "r"(af0), "r"(af1), "r"(af2), "r"(af3), "r"(0x3C003C00u));
            } else {
                af0 = wf[ks].x; af1 = wf[ks].y; af2 = wf[ks].z; af3 = wf[ks].w;
            }

            // two half-groups of (2 ldmatrix.x4 + 4 MMA) to cap live regs
            #pragma unroll
            for (int h = 0; h < 2; h++) {
                uint32_t bf[4][2];
                #pragma unroll
                for (int q = 0; q < 2; q++) {
                    uint32_t addr = sgb + (uint32_t)((h * 2 + q) * 16 * SGS + bro + jj) * 2u;
                    asm volatile("ldmatrix.sync.aligned.m8n8.x4.shared.b16 {%0,%1,%2,%3}, [%4];"
                        : "=r"(bf[2 * q][0]), "=r"(bf[2 * q][1]),
                          "=r"(bf[2 * q + 1][0]), "=r"(bf[2 * q + 1][1])
                        : "r"(addr));
                }
                #pragma unroll
                for (int nt = 0; nt < 4; nt++) {
                    asm volatile(
                        "mma.sync.aligned.m16n8k16.row.col.f32.f16.f16.f32 "
                        "{%0,%1,%2,%3}, {%4,%5,%6,%7}, {%8,%9}, {%0,%1,%2,%3};"
                        : "+f"(acc[h * 4 + nt][0]), "+f"(acc[h * 4 + nt][1]),
                          "+f"(acc[h * 4 + nt][2]), "+f"(acc[h * 4 + nt][3])
                        : "r"(af0), "r"(af1), "r"(af2), "r"(af3),
                          "r"(bf[nt][0]), "r"(bf[nt][1]));
                }
            }
        }
    }

    if (GEN && tig == 0) {
        g_den[jsplit * NN + row0] = accd[0];
        g_den[jsplit * NN + row0 + 8] = accd[2];
    }

    float* np = g_num + (size_t)jsplit * NN * DD;
    #pragma unroll
    for (int nt = 0; nt < 8; nt++) {
        *(float2*)(np + (size_t)row0 * DD + nt * 8 + tig * 2) =
            make_float2(acc[nt][0], acc[nt][1]);
        *(float2*)(np + (size_t)(row0 + 8) * DD + nt * 8 + tig * 2) =
            make_float2(acc[nt][2], acc[nt][3]);
    }
}

// ============================================================
// finalize (layer 1): V = relu(num/den + G + bs)
// ============================================================
__global__ __launch_bounds__(256) void finalize_kernel(const float* __restrict__ bs)
{
    int gid = blockIdx.x * 256 + threadIdx.x;
    int i = gid >> 6;
    float ds = 0.f, ns = 0.f;
    #pragma unroll
    for (int s = 0; s < NSPLIT; s++) {
        ds += g_den[s * NN + i];
        ns += g_num[(size_t)s * NN * DD + gid];
    }
    float v = ns / ds + g_G[gid] + bs[0];
    g_V[gid] = fmaxf(v, 0.f);
}

// ============================================================
// reduce (finalize2 fused): column sums of relu(num/den + G + bs)
// ============================================================
__global__ __launch_bounds__(256) void reduce_kernel(const float* __restrict__ bs)
{
    __shared__ float s[4][64];
    int tid = threadIdx.x;
    int k = tid & 63;
    int rg = tid >> 6;
    int bkt = blockIdx.x;
    float acc = 0.f;
    for (int r = rg; r < 128; r += 4) {
        int row = bkt * 128 + r;
        float ds = 0.f, ns = 0.f;
        #pragma unroll
        for (int sp = 0; sp < NSPLIT; sp++) {
            ds += g_den[sp * NN + row];
            ns += g_num[(size_t)sp * NN * DD + (size_t)row * DD + k];
        }
        float v = ns / ds + g_G[row * 64 + k] + bs[0];
        acc += fmaxf(v, 0.f);
    }
    s[rg][k] = acc;
    __syncthreads();
    if (tid < 64)
        g_part[bkt * 64 + tid] = s[0][tid] + s[1][tid] + s[2][tid] + s[3][tid];
}

__global__ void head_kernel(const float* __restrict__ Wl,
                            const float* __restrict__ bl,
                            float* __restrict__ out)
{
    __shared__ float sv[64];
    int t = threadIdx.x;
    float sk = 0.f;
    for (int b = 0; b < 64; b++) sk += g_part[b * 64 + t];
    sv[t] = sk * Wl[t];
    __syncthreads();
    if (t == 0) {
        float s = 0.f;
        for (int i = 0; i < 64; i++) s += sv[i];
        s += bl[0];
        out[0] = 1.f / (1.f + expf(-s));
    }
}

extern "C" void kernel_launch(void* const* d_in, const int* in_sizes, int n_in,
                              void* d_out, int out_size)
{
    const float* x     = (const float*)d_in[0];
    const float* alpha = (const float*)d_in[1];
    const float* W1    = (const float*)d_in[2];
    const float* b1    = (const float*)d_in[3];
    const float* wt1   = (const float*)d_in[4];
    const float* bs1   = (const float*)d_in[5];
    const float* W2    = (const float*)d_in[6];
    const float* b2    = (const float*)d_in[7];
    const float* wt2   = (const float*)d_in[8];
    const float* bs2   = (const float*)d_in[9];
    const float* Wl    = (const float*)d_in[10];
    const float* bl    = (const float*)d_in[11];
    float* out = (float*)d_out;

    dim3 pg(NN / MT, NSPLIT);

    ep_kernel<<<NN / 256, 256>>>(x, alpha);
    // layer 1: generate + cache weight fragments
    prep_kernel<7><<<NN / 32, 256>>>(x, W1, b1, wt1);
    pass_kernel<1><<<pg, 256>>>(alpha);
    finalize_kernel<<<NN * DD / 256, 256>>>(bs1);
    // layer 2: replay cached fragments (den reused from layer 1)
    prep_kernel<64><<<NN / 32, 256>>>(nullptr, W2, b2, wt2);
    pass_kernel<0><<<pg, 256>>>(alpha);
    // head: finalize2 fused into reduce
    reduce_kernel<<<64, 256>>>(bs2);
    head_kernel<<<1, 64>>>(Wl, bl, out);
}

// round 12
// speedup vs baseline: 1.1534x; 1.1501x over previous
#include <cuda_runtime.h>
#include <cuda_fp16.h>
#include <math.h>
#include <stdint.h>

#define NN 8192
#define DD 64
#define NSPLIT 4
#define MT 128          // rows per CTA
#define JT 128          // j tile
#define JSPAN (NN / NSPLIT)        // 2048 j's per CTA
#define NTILE (JSPAN / JT)         // 16 j-tiles per CTA
#define SGS 136         // padded sG row stride (halves)

// ---- static device scratch (no allocation allowed) ----
__device__ float  g_G[NN * DD];            // G = relu(X@W+b)@wt (fp32, row-major)
__device__ __half g_GT[DD * NN];           // G transposed, fp16 (feature-major)
__device__ float  g_V[NN * DD];            // layer-1 output
__device__ float  g_num[NSPLIT * NN * DD]; // numerator partials
__device__ float  g_den[NSPLIT * NN];      // denominator partials (pass1 only)
__device__ __half g_ephe[NN];              // scaled eta (fp16)
__device__ __half g_ephp[NN];              // scaled phi (fp16)
__device__ float  g_part[64 * 64];

// ============================================================
// ep: scaled fp16 SoA coords.  s = sqrt(alpha*log2e) so that
// 2^(-(de^2+dp^2)) == exp(-alpha*dR^2)
// ============================================================
__global__ void ep_kernel(const float* __restrict__ x, const float* __restrict__ alpha) {
    const float LOG2E = 1.44269504088896340736f;
    float s = sqrtf(alpha[0] * LOG2E);
    int j = blockIdx.x * 256 + threadIdx.x;
    g_ephe[j] = __float2half(x[j * 7 + 1] * s);
    g_ephp[j] = __float2half(x[j * 7 + 2] * s);
}

// ============================================================
// prep v2: G = relu(X@W+b)@wt, weights in SMEM, 4 cols/thread via
// float4 LDS. 16 row-slots x 16 col-groups, 32 rows/CTA, low regs.
// ============================================================
template<int DIN>
__global__ __launch_bounds__(256) void prep_kernel(
    const float* __restrict__ Xext, const float* __restrict__ W,
    const float* __restrict__ b, const float* __restrict__ wt)
{
    __shared__ float sW[DIN * 64];
    __shared__ float swt[64 * 64];
    __shared__ float sx[16][(DIN <= 8) ? 8 : 64];
    __shared__ float sh[16][64];
    __shared__ __half sgt[32][64];

    const int tid = threadIdx.x;
    const int rs = tid >> 4;       // row slot 0..15
    const int cg = tid & 15;       // col group (4 cols)
    const float* X = Xext ? Xext : g_V;
    const int rowbase = blockIdx.x * 32;

    // cooperative weight loads (float4)
    for (int t = tid; t < DIN * 16; t += 256)
        ((float4*)sW)[t] = ((const float4*)W)[t];
    for (int t = tid; t < 64 * 16; t += 256)
        ((float4*)swt)[t] = ((const float4*)wt)[t];
    const float4 bk4 = *(const float4*)&b[cg * 4];
    __syncthreads();

    #pragma unroll
    for (int half = 0; half < 2; half++) {
        const int row = rowbase + half * 16 + rs;
        // load X row into sx
        if (DIN <= 8) {
            if (cg < DIN) sx[rs][cg] = X[row * DIN + cg];
        } else {
            *(float4*)&sx[rs][cg * 4] = *(const float4*)&X[row * DIN + cg * 4];
        }
        __syncthreads();
        // stage 1: h = relu(x @ W + b), 4 cols per thread
        float a0 = bk4.x, a1 = bk4.y, a2 = bk4.z, a3 = bk4.w;
        #pragma unroll
        for (int d = 0; d < DIN; d++) {
            float xv = sx[rs][d];
            float4 w4 = *(const float4*)&sW[d * 64 + cg * 4];
            a0 = fmaf(xv, w4.x, a0); a1 = fmaf(xv, w4.y, a1);
            a2 = fmaf(xv, w4.z, a2); a3 = fmaf(xv, w4.w, a3);
        }
        *(float4*)&sh[rs][cg * 4] = make_float4(fmaxf(a0, 0.f), fmaxf(a1, 0.f),
                                                fmaxf(a2, 0.f), fmaxf(a3, 0.f));
        __syncthreads();
        // stage 2: g = h @ wt, 4 cols per thread
        float g0 = 0.f, g1 = 0.f, g2 = 0.f, g3 = 0.f;
        #pragma unroll
        for (int m = 0; m < 64; m++) {
            float hv = sh[rs][m];
            float4 w4 = *(const float4*)&swt[m * 64 + cg * 4];
            g0 = fmaf(hv, w4.x, g0); g1 = fmaf(hv, w4.y, g1);
            g2 = fmaf(hv, w4.z, g2); g3 = fmaf(hv, w4.w, g3);
        }
        *(float4*)&g_G[row * 64 + cg * 4] = make_float4(g0, g1, g2, g3);
        sgt[half * 16 + rs][cg * 4 + 0] = __float2half(g0);
        sgt[half * 16 + rs][cg * 4 + 1] = __float2half(g1);
        sgt[half * 16 + rs][cg * 4 + 2] = __float2half(g2);
        sgt[half * 16 + rs][cg * 4 + 3] = __float2half(g3);
    }
    __syncthreads();
    // coalesced transposed store: g_GT[k][rowbase..rowbase+31]
    const int kk = tid >> 2, seg = tid & 3;
    __half tmp[8];
    #pragma unroll
    for (int r = 0; r < 8; r++) tmp[r] = sgt[seg * 8 + r][kk];
    *(float4*)(g_GT + kk * NN + rowbase + seg * 8) = *(float4*)tmp;
}

// ============================================================
// wgen: half2-packed weights for a j-pair.
// drn = LL - de^2 - dp^2 ; w = 2^(2^drn) = exp(exp(-alpha dR^2))
// ============================================================
__device__ __forceinline__ uint32_t wgen(half2 ei, half2 pi, half2 ej, half2 pj,
                                         half2 tps2, half2 LL2) {
    half2 de = __hsub2(ei, ej);
    half2 d  = __hsub2(pi, pj);
    half2 ad = __habs2(d);
    half2 dp = __hmin2(ad, __hsub2(tps2, ad));
    half2 s  = __hfma2(dp, dp, __hmul2(de, de));
    half2 drn = __hsub2(LL2, s);
    uint32_t r;
    asm("{\n\t.reg .b32 t;\n\t"
        "ex2.approx.f16x2 t, %1;\n\t"
        "ex2.approx.f16x2 %0, t;\n\t}"
        : "=r"(r) : "r"(*(uint32_t*)&drn));
    return r;
}

// ============================================================
// pass: S@G on HMMA. Weights recomputed on the fly in BOTH layers
// (no fragment cache -> no 268MB DRAM round-trip).
// DEN=1 additionally accumulates the softmax denominator via an
// extra MMA against a constant ones-B fragment (layer 1 only).
// ============================================================
template<int DEN>
__global__ __launch_bounds__(256, 3) void pass_kernel(const float* __restrict__ alpha)
{
    __shared__ __half sG[64 * SGS];   // [feature][j] padded
    __shared__ __half sEe[JT];
    __shared__ __half sEp[JT];

    const int tid = threadIdx.x;
    const int warp = tid >> 5, lane = tid & 31;
    const int gid = lane >> 2, tig = lane & 3;
    const int rowtile = blockIdx.x, jsplit = blockIdx.y;
    const int j0base = jsplit * JSPAN;

    const int row0 = rowtile * MT + warp * 16 + gid;

    const float LOG2E = 1.44269504088896340736f;
    const float TWOPI = 6.28318530717958647692f;
    float tps = TWOPI * sqrtf(alpha[0] * LOG2E);
    const half2 tps2 = __half2half2(__float2half(tps));
    const half2 LL2  = __half2half2(__float2half(0.52876637294489770f));
    const half2 ei0_2 = __half2half2(g_ephe[row0]);
    const half2 pi0_2 = __half2half2(g_ephp[row0]);
    const half2 ei1_2 = __half2half2(g_ephe[row0 + 8]);
    const half2 pi1_2 = __half2half2(g_ephp[row0 + 8]);

    // ldmatrix per-lane address offset (halves)
    const int m = lane >> 3;
    const int bro = ((m >> 1) * 8 + (lane & 7)) * SGS + (m & 1) * 8;

    uint32_t sgb;
    asm("{ .reg .u64 t; cvta.to.shared.u64 t, %1; cvt.u32.u64 %0, t; }" : "=r"(sgb) : "l"(sG));

    float acc[8][4];
    #pragma unroll
    for (int nt = 0; nt < 8; nt++)
        #pragma unroll
        for (int q = 0; q < 4; q++) acc[nt][q] = 0.f;
    float accd[4] = {0.f, 0.f, 0.f, 0.f};   // den accumulator (DEN only)

    for (int t = 0; t < NTILE; t++) {
        const int j0 = j0base + t * JT;
        __syncthreads();
        #pragma unroll
        for (int i = 0; i < 4; i++) {
            int idx = tid + i * 256;
            int f = idx >> 4, c = idx & 15;
            *(float4*)(sG + f * SGS + c * 8) = *(const float4*)(g_GT + f * NN + j0 + c * 8);
        }
        if (tid < 32) {
            if (tid < 16)
                *(uint4*)(sEe + tid * 8) = *(const uint4*)(g_ephe + j0 + tid * 8);
            else
                *(uint4*)(sEp + (tid - 16) * 8) = *(const uint4*)(g_ephp + j0 + (tid - 16) * 8);
        }
        __syncthreads();

        #pragma unroll
        for (int ks = 0; ks < 8; ks++) {
            const int jj = ks * 16;
            half2 ej0 = *(const half2*)(sEe + jj + tig * 2);
            half2 pj0 = *(const half2*)(sEp + jj + tig * 2);
            half2 ej1 = *(const half2*)(sEe + jj + 8 + tig * 2);
            half2 pj1 = *(const half2*)(sEp + jj + 8 + tig * 2);
            uint32_t af0 = wgen(ei0_2, pi0_2, ej0, pj0, tps2, LL2);
            uint32_t af1 = wgen(ei1_2, pi1_2, ej0, pj0, tps2, LL2);
            uint32_t af2 = wgen(ei0_2, pi0_2, ej1, pj1, tps2, LL2);
            uint32_t af3 = wgen(ei1_2, pi1_2, ej1, pj1, tps2, LL2);
            if (DEN) {
                // den: MMA against constant all-ones B fragment
                asm volatile(
                    "mma.sync.aligned.m16n8k16.row.col.f32.f16.f16.f32 "
                    "{%0,%1,%2,%3}, {%4,%5,%6,%7}, {%8,%8}, {%0,%1,%2,%3};"
                    : "+f"(accd[0]), "+f"(accd[1]), "+f"(accd[2]), "+f"(accd[3])
                    : "r"(af0), "r"(af1), "r"(af2), "r"(af3), "r"(0x3C003C00u));
            }

            // two half-groups of (2 ldmatrix.x4 + 4 MMA) to cap live regs
            #pragma unroll
            for (int h = 0; h < 2; h++) {
                uint32_t bf[4][2];
                #pragma unroll
                for (int q = 0; q < 2; q++) {
                    uint32_t addr = sgb + (uint32_t)((h * 2 + q) * 16 * SGS + bro + jj) * 2u;
                    asm volatile("ldmatrix.sync.aligned.m8n8.x4.shared.b16 {%0,%1,%2,%3}, [%4];"
                        : "=r"(bf[2 * q][0]), "=r"(bf[2 * q][1]),
                          "=r"(bf[2 * q + 1][0]), "=r"(bf[2 * q + 1][1])
                        : "r"(addr));
                }
                #pragma unroll
                for (int nt = 0; nt < 4; nt++) {
                    asm volatile(
                        "mma.sync.aligned.m16n8k16.row.col.f32.f16.f16.f32 "
                        "{%0,%1,%2,%3}, {%4,%5,%6,%7}, {%8,%9}, {%0,%1,%2,%3};"
                        : "+f"(acc[h * 4 + nt][0]), "+f"(acc[h * 4 + nt][1]),
                          "+f"(acc[h * 4 + nt][2]), "+f"(acc[h * 4 + nt][3])
                        : "r"(af0), "r"(af1), "r"(af2), "r"(af3),
                          "r"(bf[nt][0]), "r"(bf[nt][1]));
                }
            }
        }
    }

    if (DEN && tig == 0) {
        g_den[jsplit * NN + row0] = accd[0];
        g_den[jsplit * NN + row0 + 8] = accd[2];
    }

    float* np = g_num + (size_t)jsplit * NN * DD;
    #pragma unroll
    for (int nt = 0; nt < 8; nt++) {
        *(float2*)(np + (size_t)row0 * DD + nt * 8 + tig * 2) =
            make_float2(acc[nt][0], acc[nt][1]);
        *(float2*)(np + (size_t)(row0 + 8) * DD + nt * 8 + tig * 2) =
            make_float2(acc[nt][2], acc[nt][3]);
    }
}

// ============================================================
// finalize (layer 1): V = relu(num/den + G + bs)
// ============================================================
__global__ __launch_bounds__(256) void finalize_kernel(const float* __restrict__ bs)
{
    int gid = blockIdx.x * 256 + threadIdx.x;
    int i = gid >> 6;
    float ds = 0.f, ns = 0.f;
    #pragma unroll
    for (int s = 0; s < NSPLIT; s++) {
        ds += g_den[s * NN + i];
        ns += g_num[(size_t)s * NN * DD + gid];
    }
    float v = ns / ds + g_G[gid] + bs[0];
    g_V[gid] = fmaxf(v, 0.f);
}

// ============================================================
// reduce (finalize2 fused): column sums of relu(num/den + G + bs)
// ============================================================
__global__ __launch_bounds__(256) void reduce_kernel(const float* __restrict__ bs)
{
    __shared__ float s[4][64];
    int tid = threadIdx.x;
    int k = tid & 63;
    int rg = tid >> 6;
    int bkt = blockIdx.x;
    float acc = 0.f;
    for (int r = rg; r < 128; r += 4) {
        int row = bkt * 128 + r;
        float ds = 0.f, ns = 0.f;
        #pragma unroll
        for (int sp = 0; sp < NSPLIT; sp++) {
            ds += g_den[sp * NN + row];
            ns += g_num[(size_t)sp * NN * DD + (size_t)row * DD + k];
        }
        float v = ns / ds + g_G[row * 64 + k] + bs[0];
        acc += fmaxf(v, 0.f);
    }
    s[rg][k] = acc;
    __syncthreads();
    if (tid < 64)
        g_part[bkt * 64 + tid] = s[0][tid] + s[1][tid] + s[2][tid] + s[3][tid];
}

__global__ void head_kernel(const float* __restrict__ Wl,
                            const float* __restrict__ bl,
                            float* __restrict__ out)
{
    __shared__ float sv[64];
    int t = threadIdx.x;
    float sk = 0.f;
    for (int b = 0; b < 64; b++) sk += g_part[b * 64 + t];
    sv[t] = sk * Wl[t];
    __syncthreads();
    if (t == 0) {
        float s = 0.f;
        for (int i = 0; i < 64; i++) s += sv[i];
        s += bl[0];
        out[0] = 1.f / (1.f + expf(-s));
    }
}

extern "C" void kernel_launch(void* const* d_in, const int* in_sizes, int n_in,
                              void* d_out, int out_size)
{
    const float* x     = (const float*)d_in[0];
    const float* alpha = (const float*)d_in[1];
    const float* W1    = (const float*)d_in[2];
    const float* b1    = (const float*)d_in[3];
    const float* wt1   = (const float*)d_in[4];
    const float* bs1   = (const float*)d_in[5];
    const float* W2    = (const float*)d_in[6];
    const float* b2    = (const float*)d_in[7];
    const float* wt2   = (const float*)d_in[8];
    const float* bs2   = (const float*)d_in[9];
    const float* Wl    = (const float*)d_in[10];
    const float* bl    = (const float*)d_in[11];
    float* out = (float*)d_out;

    dim3 pg(NN / MT, NSPLIT);

    ep_kernel<<<NN / 256, 256>>>(x, alpha);
    // layer 1: weights on the fly, den accumulated
    prep_kernel<7><<<NN / 32, 256>>>(x, W1, b1, wt1);
    pass_kernel<1><<<pg, 256>>>(alpha);
    finalize_kernel<<<NN * DD / 256, 256>>>(bs1);
    // layer 2: weights recomputed on the fly, den reused from layer 1
    prep_kernel<64><<<NN / 32, 256>>>(nullptr, W2, b2, wt2);
    pass_kernel<0><<<pg, 256>>>(alpha);
    // head: finalize2 fused into reduce
    reduce_kernel<<<64, 256>>>(bs2);
    head_kernel<<<1, 64>>>(Wl, bl, out);
}